// round 15
// baseline (speedup 1.0000x reference)
#include <cuda_runtime.h>

#define T_LEVELS    21
#define IN_DIM      4096
#define OUT_DIM     32
#define BLK_BITS    13         // levels 0..12, bits of prefix P
#define PPB         8          // prefixes per block (= warps per block)
#define N_PRE       (4 + OUT_DIM)
#define N_PART      4          // precompute partial splits per row
#define NPREF       (1 << BLK_BITS)      // 8192 prefixes
#define MAP_STRIDE  168        // per-prefix floats: 5*32 coeffs + R(4) + r(2), padded
#define MAP_BLOCKS  512        // 16 prefixes per block (2 per warp)

// Scratch (allowed: __device__ globals, no alloc).
__device__ float g_part[N_PRE * N_PART];
__device__ float g_maps[(size_t)NPREF * MAP_STRIDE];   // ~5.5 MB

// ---------------------------------------------------------------------------
// Kernel 1 (two independent halves, one node):
//   blocks 0..143: 36 dot products of x with in_left/in_right/out_layer0 rows,
//                  split 4-ways per row (needs x; writes g_part).
//   blocks 144..655: composed affine maps of tree levels 0..12 for all 8192
//                  prefixes (does NOT need x; writes g_maps):
//                    v13    = R·v0 + r
//                    A13[c] = A0[c] + pa_c·v0ax + qa_c·v0ay
//                                   + pb_c·v0bx + qb_c·v0by + kk_c
// ---------------------------------------------------------------------------
__global__ void precompute_kernel(const float* __restrict__ x,
                                  const float* __restrict__ wl,
                                  const float* __restrict__ wr,
                                  const float* __restrict__ bl,
                                  const float* __restrict__ br,
                                  const float* __restrict__ w0,
                                  const float* __restrict__ ob,
                                  const float* __restrict__ tl,
                                  const float* __restrict__ tr,
                                  const float* __restrict__ tbl,
                                  const float* __restrict__ tbr,
                                  const float* __restrict__ wout)
{
    __shared__ float s_red[8];
    __shared__ float s_w[BLK_BITS * 64];   // wout levels 0..12
    __shared__ float s_t[BLK_BITS * 12];   // tree maps levels 0..12

    if (blockIdx.x < N_PRE * N_PART) {
        // ---- dot-product half ----
        int r = blockIdx.x >> 2;       // 0..35
        int j = blockIdx.x & 3;        // part 0..3
        const float* src;
        if (r < 2)       src = wl + r * IN_DIM;
        else if (r < 4)  src = wr + (r - 2) * IN_DIM;
        else             src = w0 + (r - 4) * IN_DIM;

        const float4* x4 = reinterpret_cast<const float4*>(x) + j * 256;
        const float4* s4 = reinterpret_cast<const float4*>(src) + j * 256;
        float4 a = x4[threadIdx.x], b = s4[threadIdx.x];
        float s = fmaf(a.x, b.x, fmaf(a.y, b.y, fmaf(a.z, b.z, a.w * b.w)));

        #pragma unroll
        for (int o = 16; o > 0; o >>= 1) s += __shfl_down_sync(0xffffffffu, s, o);
        if ((threadIdx.x & 31) == 0) s_red[threadIdx.x >> 5] = s;
        __syncthreads();
        if (threadIdx.x == 0) {
            float tot = 0.0f;
            #pragma unroll
            for (int ww = 0; ww < 8; ww++) tot += s_red[ww];
            if (j == 0) {
                if (r < 2)      tot += bl[r];
                else if (r < 4) tot += br[r - 2];
                else            tot += ob[r - 4];
            }
            g_part[r * N_PART + j] = tot;
        }
        return;
    }

    // ---- map half: compose levels 0..12 per prefix ----
    for (int i = threadIdx.x; i < BLK_BITS * 64; i += blockDim.x)
        s_w[i] = wout[i];
    for (int i = threadIdx.x; i < BLK_BITS * 12; i += blockDim.x) {
        int k = i / 12, rem = i % 12, b = rem / 6, e = rem % 6;
        const float* M = b ? tr  : tl;
        const float* B = b ? tbr : tbl;
        s_t[i] = (e < 4) ? M[k * 4 + e] : B[k * 2 + (e - 4)];
    }
    __syncthreads();

    const float2* s_w2 = reinterpret_cast<const float2*>(s_w);
    const int m = blockIdx.x - N_PRE * N_PART;     // 0..511
    const unsigned w = threadIdx.x >> 5;
    const unsigned lane = threadIdx.x & 31u;

    #pragma unroll
    for (int q = 0; q < 2; q++) {
        const unsigned P = (unsigned)m * 16 + w * 2 + q;
        float R00 = 1.f, R01 = 0.f, R10 = 0.f, R11 = 1.f, r0 = 0.f, r1 = 0.f;
        float pa = 0.f, qa = 0.f, pb = 0.f, qb = 0.f, kk = 0.f;
        #pragma unroll 1
        for (int k = 0; k < BLK_BITS; k++) {
            unsigned b = (P >> k) & 1u;
            float sA = b ? 0.f : 1.f;
            float sB = b ? 1.f : 0.f;
            float2 w2 = s_w2[k * 32 + lane];
            float wRx = fmaf(w2.x, R00, w2.y * R10);
            float wRy = fmaf(w2.x, R01, w2.y * R11);
            float kc  = fmaf(w2.x, r0,  w2.y * r1);
            pa = fmaf(sA, wRx, pa);
            qa = fmaf(sA, wRy, qa);
            pb = fmaf(sB, wRx, pb);
            qb = fmaf(sB, wRy, qb);
            kk += kc;
            const float* M = s_t + k * 12 + b * 6;  // warp-uniform -> broadcast
            float m00 = M[0], m01 = M[1], m10 = M[2], m11 = M[3], c0 = M[4], c1 = M[5];
            float n00 = fmaf(m00, R00, m01 * R10), n01 = fmaf(m00, R01, m01 * R11);
            float n10 = fmaf(m10, R00, m11 * R10), n11 = fmaf(m10, R01, m11 * R11);
            float nr0 = fmaf(m00, r0, fmaf(m01, r1, c0));
            float nr1 = fmaf(m10, r0, fmaf(m11, r1, c1));
            R00 = n00; R01 = n01; R10 = n10; R11 = n11; r0 = nr0; r1 = nr1;
        }
        float* g = g_maps + (size_t)P * MAP_STRIDE;
        g[lane]       = pa;
        g[32 + lane]  = qa;
        g[64 + lane]  = pb;
        g[96 + lane]  = qb;
        g[128 + lane] = kk;
        if (lane == 0) {
            g[160] = R00; g[161] = R01; g[162] = R10; g[163] = R11;
            g[164] = r0;  g[165] = r1;
        }
    }
}

// ---------------------------------------------------------------------------
// Kernel 2 (R11 body, phase 1 replaced by precomputed-map application):
//   Phase 1: warp w loads the composed 13-level map for prefix Pb+w (5
//            coalesced LDG.32 per lane + 6 broadcast) and applies it to
//            (A0, v0) -> s_A13[w]/s_v13[w]. No serial walk.
//   Composition: levels 13..17 folded into a per-thread affine map.
//   Phase 2 (it=0..7): affine jump to level 18, register-hoisted suffix
//   (levels 18..20), 8 rows/it via fully-coalesced STG.128 (__stcs).
// Row index: p = (Pb+it) | (w<<13) | (rr<<16) | (b1<<18) | (b2<<19), leaf=bit20.
// ---------------------------------------------------------------------------
__global__ void __launch_bounds__(256, 2)
tree_kernel(const float* __restrict__ tl,   // (21,2,2)
            const float* __restrict__ tr,   // (21,2,2)
            const float* __restrict__ tbl,  // (21,2)
            const float* __restrict__ tbr,  // (21,2)
            const float* __restrict__ wout, // (21,32,2)
            float* __restrict__ out)
{
    __shared__ float s_wout[T_LEVELS * 64];  // [k][c][j]
    __shared__ float s_tree[T_LEVELS * 12];  // [k][branch]{m00,m01,m10,m11,b0,b1}
    __shared__ float s_pre[N_PRE];
    __shared__ __align__(16) float s_A13[PPB][OUT_DIM];
    __shared__ __align__(16) float s_v13[PPB][4];

    for (int i = threadIdx.x; i < T_LEVELS * 64; i += blockDim.x)
        s_wout[i] = wout[i];
    for (int i = threadIdx.x; i < T_LEVELS * 12; i += blockDim.x) {
        int k = i / 12, rem = i % 12, b = rem / 6, e = rem % 6;
        const float* M = b ? tr  : tl;
        const float* B = b ? tbr : tbl;
        s_tree[i] = (e < 4) ? M[k * 4 + e] : B[k * 2 + (e - 4)];
    }
    for (int i = threadIdx.x; i < N_PRE; i += blockDim.x)
        s_pre[i] = g_part[i * N_PART + 0] + g_part[i * N_PART + 1]
                 + g_part[i * N_PART + 2] + g_part[i * N_PART + 3];
    __syncthreads();

    const float2* s_wout2 = reinterpret_cast<const float2*>(s_wout);
    const unsigned w    = threadIdx.x >> 5;        // warp id: level 13..15 bits
    const unsigned lane = threadIdx.x & 31u;
    const unsigned Pb   = blockIdx.x * PPB;

    // ---- phase 1: apply precomputed 13-level map for prefix Pb + w ----
    {
        const unsigned P = Pb + w;
        const float* g = g_maps + (size_t)P * MAP_STRIDE;
        const float v0ax = s_pre[0], v0ay = s_pre[2];
        const float v0bx = s_pre[1], v0by = s_pre[3];
        float pa = g[lane],       qa = g[32 + lane];
        float pb = g[64 + lane],  qb = g[96 + lane];
        float kk = g[128 + lane];
        float A = fmaf(pa, v0ax, fmaf(qa, v0ay,
                  fmaf(pb, v0bx, fmaf(qb, v0by, s_pre[4 + lane] + kk))));
        s_A13[w][lane] = A;
        if (lane == 0) {
            float R00 = g[160], R01 = g[161], R10 = g[162], R11 = g[163];
            float r0  = g[164], r1  = g[165];
            float4 v4;
            v4.x = fmaf(R00, v0ax, fmaf(R01, v0ay, r0));
            v4.y = fmaf(R10, v0ax, fmaf(R11, v0ay, r1));
            v4.z = fmaf(R00, v0bx, fmaf(R01, v0by, r0));
            v4.w = fmaf(R10, v0bx, fmaf(R11, v0by, r1));
            *reinterpret_cast<float4*>(&s_v13[w][0]) = v4;
        }
    }

    const unsigned c4 = lane & 7u;                 // channel group (4 channels)
    const unsigned rr = lane >> 3;                 // 2 bits: levels 16..17

    // ---- per-thread affine composition of levels 13..17 (it-invariant) ----
    float R00 = 1.f, R01 = 0.f, R10 = 0.f, R11 = 1.f, rc0 = 0.f, rc1 = 0.f;
    float pa0 = 0.f, pa1 = 0.f, pa2 = 0.f, pa3 = 0.f;
    float qa0 = 0.f, qa1 = 0.f, qa2 = 0.f, qa3 = 0.f;
    float pb0 = 0.f, pb1 = 0.f, pb2 = 0.f, pb3 = 0.f;
    float qb0 = 0.f, qb1 = 0.f, qb2 = 0.f, qb3 = 0.f;
    float kk0 = 0.f, kk1 = 0.f, kk2 = 0.f, kk3 = 0.f;
    #pragma unroll
    for (int j = 0; j < 5; j++) {
        const int k = BLK_BITS + j;                 // 13..17
        unsigned b = (j < 3) ? ((w >> j) & 1u) : ((rr >> (j - 3)) & 1u);
        float sA = b ? 0.f : 1.f;
        float sB = b ? 1.f : 0.f;
        const float2* W = s_wout2 + k * 32 + c4 * 4;
        #pragma unroll
        for (int i = 0; i < 4; i++) {
            float2 w2 = W[i];
            float wRx = fmaf(w2.x, R00, w2.y * R10);
            float wRy = fmaf(w2.x, R01, w2.y * R11);
            float kc  = fmaf(w2.x, rc0, w2.y * rc1);
            float* PA = (i == 0) ? &pa0 : (i == 1) ? &pa1 : (i == 2) ? &pa2 : &pa3;
            float* QA = (i == 0) ? &qa0 : (i == 1) ? &qa1 : (i == 2) ? &qa2 : &qa3;
            float* PB = (i == 0) ? &pb0 : (i == 1) ? &pb1 : (i == 2) ? &pb2 : &pb3;
            float* QB = (i == 0) ? &qb0 : (i == 1) ? &qb1 : (i == 2) ? &qb2 : &qb3;
            float* KK = (i == 0) ? &kk0 : (i == 1) ? &kk1 : (i == 2) ? &kk2 : &kk3;
            *PA = fmaf(sA, wRx, *PA);
            *QA = fmaf(sA, wRy, *QA);
            *PB = fmaf(sB, wRx, *PB);
            *QB = fmaf(sB, wRy, *QB);
            *KK += kc;
        }
        const float* M = s_tree + k * 12 + b * 6;
        float m00 = M[0], m01 = M[1], m10 = M[2], m11 = M[3], c0 = M[4], c1 = M[5];
        float n00 = fmaf(m00, R00, m01 * R10), n01 = fmaf(m00, R01, m01 * R11);
        float n10 = fmaf(m10, R00, m11 * R10), n11 = fmaf(m10, R01, m11 * R11);
        float nr0 = fmaf(m00, rc0, fmaf(m01, rc1, c0));
        float nr1 = fmaf(m10, rc0, fmaf(m11, rc1, c1));
        R00 = n00; R01 = n01; R10 = n10; R11 = n11; rc0 = nr0; rc1 = nr1;
    }

    // ---- hoist ALL suffix constants (levels 18..20) into registers ----
    const float2* W18 = s_wout2 + 18 * 32 + c4 * 4;
    const float2* W19 = s_wout2 + 19 * 32 + c4 * 4;
    const float2* W20 = s_wout2 + 20 * 32 + c4 * 4;
    float2 u18a = W18[0], u18b = W18[1], u18c = W18[2], u18d = W18[3];
    float2 u19a = W19[0], u19b = W19[1], u19c = W19[2], u19d = W19[3];
    float2 u20a = W20[0], u20b = W20[1], u20c = W20[2], u20d = W20[3];
    float M18[12], M19[12];
    #pragma unroll
    for (int i = 0; i < 12; i++) M18[i] = s_tree[18 * 12 + i];
    #pragma unroll
    for (int i = 0; i < 12; i++) M19[i] = s_tree[19 * 12 + i];

    __syncthreads();

    // ---- phase 2: expand each of the 8 checkpoints ----
    #pragma unroll 1
    for (int it = 0; it < PPB; ++it) {
        const float4 af = *reinterpret_cast<const float4*>(&s_A13[it][c4 * 4]);
        const float4 vf = *reinterpret_cast<const float4*>(&s_v13[it][0]);
        const float v13ax = vf.x, v13ay = vf.y, v13bx = vf.z, v13by = vf.w;

        // jump to level 18 via the composed affine map
        float A0 = fmaf(pa0, v13ax, fmaf(qa0, v13ay, fmaf(pb0, v13bx, fmaf(qb0, v13by, af.x + kk0))));
        float A1 = fmaf(pa1, v13ax, fmaf(qa1, v13ay, fmaf(pb1, v13bx, fmaf(qb1, v13by, af.y + kk1))));
        float A2 = fmaf(pa2, v13ax, fmaf(qa2, v13ay, fmaf(pb2, v13bx, fmaf(qb2, v13by, af.z + kk2))));
        float A3 = fmaf(pa3, v13ax, fmaf(qa3, v13ay, fmaf(pb3, v13bx, fmaf(qb3, v13by, af.w + kk3))));
        float vax = fmaf(R00, v13ax, fmaf(R01, v13ay, rc0));
        float vay = fmaf(R10, v13ax, fmaf(R11, v13ay, rc1));
        float vbx = fmaf(R00, v13bx, fmaf(R01, v13by, rc0));
        float vby = fmaf(R10, v13bx, fmaf(R11, v13by, rc1));

        const unsigned p_base = (Pb + it) | (w << 13) | (rr << 16);

        // suffix enumeration: b1 = s19 (level 18), b2 = s20 (level 19)
        #pragma unroll
        for (unsigned u = 0; u < 4; ++u) {
            const unsigned b1 = u & 1u, b2 = (u >> 1) & 1u;

            float vs18x = b1 ? vbx : vax;
            float vs18y = b1 ? vby : vay;
            float m00 = M18[b1 * 6 + 0], m01 = M18[b1 * 6 + 1];
            float m10 = M18[b1 * 6 + 2], m11 = M18[b1 * 6 + 3];
            float c0  = M18[b1 * 6 + 4], c1  = M18[b1 * 6 + 5];
            float pax = fmaf(m00, vax, fmaf(m01, vay, c0));
            float pay = fmaf(m10, vax, fmaf(m11, vay, c1));
            float pbx = fmaf(m00, vbx, fmaf(m01, vby, c0));
            float pby = fmaf(m10, vbx, fmaf(m11, vby, c1));

            float vs19x = b2 ? pbx : pax;
            float vs19y = b2 ? pby : pay;
            m00 = M19[b2 * 6 + 0]; m01 = M19[b2 * 6 + 1];
            m10 = M19[b2 * 6 + 2]; m11 = M19[b2 * 6 + 3];
            c0  = M19[b2 * 6 + 4]; c1  = M19[b2 * 6 + 5];
            float qax = fmaf(m00, pax, fmaf(m01, pay, c0));
            float qay = fmaf(m10, pax, fmaf(m11, pay, c1));
            float qbx = fmaf(m00, pbx, fmaf(m01, pby, c0));
            float qby = fmaf(m10, pbx, fmaf(m11, pby, c1));

            float P0 = fmaf(u19a.x, vs19x, fmaf(u19a.y, vs19y,
                       fmaf(u18a.x, vs18x, fmaf(u18a.y, vs18y, A0))));
            float P1 = fmaf(u19b.x, vs19x, fmaf(u19b.y, vs19y,
                       fmaf(u18b.x, vs18x, fmaf(u18b.y, vs18y, A1))));
            float P2 = fmaf(u19c.x, vs19x, fmaf(u19c.y, vs19y,
                       fmaf(u18c.x, vs18x, fmaf(u18c.y, vs18y, A2))));
            float P3 = fmaf(u19d.x, vs19x, fmaf(u19d.y, vs19y,
                       fmaf(u18d.x, vs18x, fmaf(u18d.y, vs18y, A3))));

            unsigned p = p_base | (b1 << 18) | (b2 << 19);
            float* o = out + (size_t)p * OUT_DIM + c4 * 4;

            float4 r0, r1;
            r0.x = fmaf(u20a.x, qax, fmaf(u20a.y, qay, P0));
            r0.y = fmaf(u20b.x, qax, fmaf(u20b.y, qay, P1));
            r0.z = fmaf(u20c.x, qax, fmaf(u20c.y, qay, P2));
            r0.w = fmaf(u20d.x, qax, fmaf(u20d.y, qay, P3));
            r1.x = fmaf(u20a.x, qbx, fmaf(u20a.y, qby, P0));
            r1.y = fmaf(u20b.x, qbx, fmaf(u20b.y, qby, P1));
            r1.z = fmaf(u20c.x, qbx, fmaf(u20c.y, qby, P2));
            r1.w = fmaf(u20d.x, qbx, fmaf(u20d.y, qby, P3));

            __stcs(reinterpret_cast<float4*>(o), r0);
            __stcs(reinterpret_cast<float4*>(o + ((size_t)1u << 20) * OUT_DIM), r1);
        }
    }
}

// ---------------------------------------------------------------------------
extern "C" void kernel_launch(void* const* d_in, const int* in_sizes, int n_in,
                              void* d_out, int out_size)
{
    const float* x    = (const float*)d_in[0];
    const float* wl   = (const float*)d_in[1];
    const float* wr   = (const float*)d_in[2];
    const float* bl   = (const float*)d_in[3];
    const float* br   = (const float*)d_in[4];
    const float* tl   = (const float*)d_in[5];
    const float* tr   = (const float*)d_in[6];
    const float* tbl  = (const float*)d_in[7];
    const float* tbr  = (const float*)d_in[8];
    const float* w0   = (const float*)d_in[9];
    const float* wout = (const float*)d_in[10];
    const float* ob   = (const float*)d_in[11];

    precompute_kernel<<<N_PRE * N_PART + MAP_BLOCKS, 256>>>(
        x, wl, wr, bl, br, w0, ob, tl, tr, tbl, tbr, wout);

    tree_kernel<<<NPREF / PPB, 256>>>(tl, tr, tbl, tbr, wout, (float*)d_out);
}

// round 16
// speedup vs baseline: 1.1343x; 1.1343x over previous
#include <cuda_runtime.h>

#define T_LEVELS    21
#define IN_DIM      4096
#define OUT_DIM     32
#define BLK_BITS    13         // levels 0..12, bits of prefix P
#define PPB         8          // prefixes per block (= warps per block)
#define N_PRE       (4 + OUT_DIM)
#define N_PART      4          // precompute partial splits per row

// Scratch: partial dot products (allowed: __device__ global, no alloc).
__device__ float g_part[N_PRE * N_PART];

// ---------------------------------------------------------------------------
// Kernel 1: 36 dot products of x (4096) with rows of in_left/in_right/out_layer0,
// split 4-ways per row for latency (144 fully-parallel small blocks).
// ---------------------------------------------------------------------------
__global__ void precompute_kernel(const float* __restrict__ x,
                                  const float* __restrict__ wl,
                                  const float* __restrict__ wr,
                                  const float* __restrict__ bl,
                                  const float* __restrict__ br,
                                  const float* __restrict__ w0,
                                  const float* __restrict__ ob)
{
    int r = blockIdx.x >> 2;       // 0..35
    int j = blockIdx.x & 3;        // part 0..3
    const float* src;
    if (r < 2)       src = wl + r * IN_DIM;
    else if (r < 4)  src = wr + (r - 2) * IN_DIM;
    else             src = w0 + (r - 4) * IN_DIM;

    const float4* x4 = reinterpret_cast<const float4*>(x) + j * 256;
    const float4* s4 = reinterpret_cast<const float4*>(src) + j * 256;
    float4 a = x4[threadIdx.x], b = s4[threadIdx.x];
    float s = fmaf(a.x, b.x, fmaf(a.y, b.y, fmaf(a.z, b.z, a.w * b.w)));

    __shared__ float red[8];
    #pragma unroll
    for (int o = 16; o > 0; o >>= 1) s += __shfl_down_sync(0xffffffffu, s, o);
    if ((threadIdx.x & 31) == 0) red[threadIdx.x >> 5] = s;
    __syncthreads();
    if (threadIdx.x == 0) {
        float tot = 0.0f;
        #pragma unroll
        for (int ww = 0; ww < 8; ww++) tot += red[ww];
        if (j == 0) {
            if (r < 2)      tot += bl[r];
            else if (r < 4) tot += br[r - 2];
            else            tot += ob[r - 4];
        }
        g_part[r * N_PART + j] = tot;
    }
}

// ---------------------------------------------------------------------------
// Kernel 2 (measured optimum, R11): hierarchical binary-tree expansion,
// 8 prefixes per block.
//   Phase 1 (parallel): warp w computes the 13-level checkpoint for prefix
//       P = blockIdx*8 + w into s_A13[w]/s_v13[w].
//   Per-thread precompute: levels 13..17 (branch bits w, rr it-invariant)
//       composed into one affine map:
//          v18    = R·v13 + r
//          A18[c] = A13[c] + pa_c·vax + qa_c·vay + pb_c·vbx + qb_c·vby + k_c
//   Phase 2 (it=0..7): 2×LDS.128 + ~28 FMA to level 18, then the fully
//       register-hoisted suffix (levels 18..20) emits 8 rows via STG.128.
// Row index: p = (Pb+it) | (w<<13) | (rr<<16) | (b1<<18) | (b2<<19), leaf=bit20.
// Store: 8 lanes (c4 = lane&7) cover one full 128B row line.
// ---------------------------------------------------------------------------
__global__ void __launch_bounds__(256, 2)
tree_kernel(const float* __restrict__ tl,   // (21,2,2)
            const float* __restrict__ tr,   // (21,2,2)
            const float* __restrict__ tbl,  // (21,2)
            const float* __restrict__ tbr,  // (21,2)
            const float* __restrict__ wout, // (21,32,2)
            float* __restrict__ out)
{
    __shared__ float s_wout[T_LEVELS * 64];  // [k][c][j]
    __shared__ float s_tree[T_LEVELS * 12];  // [k][branch]{m00,m01,m10,m11,b0,b1}
    __shared__ float s_pre[N_PRE];
    __shared__ __align__(16) float s_A13[PPB][OUT_DIM];
    __shared__ __align__(16) float s_v13[PPB][4];

    for (int i = threadIdx.x; i < T_LEVELS * 64; i += blockDim.x)
        s_wout[i] = wout[i];
    for (int i = threadIdx.x; i < T_LEVELS * 12; i += blockDim.x) {
        int k = i / 12, rem = i % 12, b = rem / 6, e = rem % 6;
        const float* M = b ? tr  : tl;
        const float* B = b ? tbr : tbl;
        s_tree[i] = (e < 4) ? M[k * 4 + e] : B[k * 2 + (e - 4)];
    }
    for (int i = threadIdx.x; i < N_PRE; i += blockDim.x)
        s_pre[i] = g_part[i * N_PART + 0] + g_part[i * N_PART + 1]
                 + g_part[i * N_PART + 2] + g_part[i * N_PART + 3];
    __syncthreads();

    const float2* s_wout2 = reinterpret_cast<const float2*>(s_wout);
    const unsigned w    = threadIdx.x >> 5;        // warp id: phase-1 owner AND level 13..15 bits
    const unsigned lane = threadIdx.x & 31u;
    const unsigned Pb   = blockIdx.x * PPB;

    // ---- phase 1 (parallel): warp w computes checkpoint for prefix Pb + w ----
    {
        const unsigned P = Pb + w;
        int c = lane;                               // lane = channel
        float A = s_pre[4 + c];
        float vax = s_pre[0], vay = s_pre[2];
        float vbx = s_pre[1], vby = s_pre[3];
        #pragma unroll 1
        for (int k = 0; k < BLK_BITS; k++) {
            unsigned b = (P >> k) & 1u;
            float2 wv = s_wout2[k * 32 + c];
            float vsx = b ? vbx : vax;
            float vsy = b ? vby : vay;
            A = fmaf(wv.x, vsx, fmaf(wv.y, vsy, A));
            const float* M = s_tree + k * 12 + b * 6;
            float m00 = M[0], m01 = M[1], m10 = M[2], m11 = M[3], c0 = M[4], c1 = M[5];
            float nax = fmaf(m00, vax, fmaf(m01, vay, c0));
            float nay = fmaf(m10, vax, fmaf(m11, vay, c1));
            float nbx = fmaf(m00, vbx, fmaf(m01, vby, c0));
            float nby = fmaf(m10, vbx, fmaf(m11, vby, c1));
            vax = nax; vay = nay; vbx = nbx; vby = nby;
        }
        s_A13[w][c] = A;
        if (lane == 0) {
            float4 v4; v4.x = vax; v4.y = vay; v4.z = vbx; v4.w = vby;
            *reinterpret_cast<float4*>(&s_v13[w][0]) = v4;
        }
    }

    const unsigned c4 = lane & 7u;                 // channel group (4 channels)
    const unsigned rr = lane >> 3;                 // 2 bits: levels 16..17

    // ---- per-thread affine composition of levels 13..17 (it-invariant) ----
    float R00 = 1.f, R01 = 0.f, R10 = 0.f, R11 = 1.f, rc0 = 0.f, rc1 = 0.f;
    float pa0 = 0.f, pa1 = 0.f, pa2 = 0.f, pa3 = 0.f;
    float qa0 = 0.f, qa1 = 0.f, qa2 = 0.f, qa3 = 0.f;
    float pb0 = 0.f, pb1 = 0.f, pb2 = 0.f, pb3 = 0.f;
    float qb0 = 0.f, qb1 = 0.f, qb2 = 0.f, qb3 = 0.f;
    float kk0 = 0.f, kk1 = 0.f, kk2 = 0.f, kk3 = 0.f;
    #pragma unroll
    for (int j = 0; j < 5; j++) {
        const int k = BLK_BITS + j;                 // 13..17
        unsigned b = (j < 3) ? ((w >> j) & 1u) : ((rr >> (j - 3)) & 1u);
        float sA = b ? 0.f : 1.f;
        float sB = b ? 1.f : 0.f;
        const float2* W = s_wout2 + k * 32 + c4 * 4;
        #pragma unroll
        for (int i = 0; i < 4; i++) {
            float2 w2 = W[i];
            float wRx = fmaf(w2.x, R00, w2.y * R10);
            float wRy = fmaf(w2.x, R01, w2.y * R11);
            float kc  = fmaf(w2.x, rc0, w2.y * rc1);
            float* PA = (i == 0) ? &pa0 : (i == 1) ? &pa1 : (i == 2) ? &pa2 : &pa3;
            float* QA = (i == 0) ? &qa0 : (i == 1) ? &qa1 : (i == 2) ? &qa2 : &qa3;
            float* PB = (i == 0) ? &pb0 : (i == 1) ? &pb1 : (i == 2) ? &pb2 : &pb3;
            float* QB = (i == 0) ? &qb0 : (i == 1) ? &qb1 : (i == 2) ? &qb2 : &qb3;
            float* KK = (i == 0) ? &kk0 : (i == 1) ? &kk1 : (i == 2) ? &kk2 : &kk3;
            *PA = fmaf(sA, wRx, *PA);
            *QA = fmaf(sA, wRy, *QA);
            *PB = fmaf(sB, wRx, *PB);
            *QB = fmaf(sB, wRy, *QB);
            *KK += kc;
        }
        const float* M = s_tree + k * 12 + b * 6;
        float m00 = M[0], m01 = M[1], m10 = M[2], m11 = M[3], c0 = M[4], c1 = M[5];
        float n00 = fmaf(m00, R00, m01 * R10), n01 = fmaf(m00, R01, m01 * R11);
        float n10 = fmaf(m10, R00, m11 * R10), n11 = fmaf(m10, R01, m11 * R11);
        float nr0 = fmaf(m00, rc0, fmaf(m01, rc1, c0));
        float nr1 = fmaf(m10, rc0, fmaf(m11, rc1, c1));
        R00 = n00; R01 = n01; R10 = n10; R11 = n11; rc0 = nr0; rc1 = nr1;
    }

    // ---- hoist ALL suffix constants (levels 18..20) into registers ----
    const float2* W18 = s_wout2 + 18 * 32 + c4 * 4;
    const float2* W19 = s_wout2 + 19 * 32 + c4 * 4;
    const float2* W20 = s_wout2 + 20 * 32 + c4 * 4;
    float2 u18a = W18[0], u18b = W18[1], u18c = W18[2], u18d = W18[3];
    float2 u19a = W19[0], u19b = W19[1], u19c = W19[2], u19d = W19[3];
    float2 u20a = W20[0], u20b = W20[1], u20c = W20[2], u20d = W20[3];
    float M18[12], M19[12];
    #pragma unroll
    for (int i = 0; i < 12; i++) M18[i] = s_tree[18 * 12 + i];
    #pragma unroll
    for (int i = 0; i < 12; i++) M19[i] = s_tree[19 * 12 + i];

    __syncthreads();

    // ---- phase 2: expand each of the 8 checkpoints ----
    #pragma unroll 1
    for (int it = 0; it < PPB; ++it) {
        const float4 af = *reinterpret_cast<const float4*>(&s_A13[it][c4 * 4]);
        const float4 vf = *reinterpret_cast<const float4*>(&s_v13[it][0]);
        const float v13ax = vf.x, v13ay = vf.y, v13bx = vf.z, v13by = vf.w;

        // jump to level 18 via the composed affine map
        float A0 = fmaf(pa0, v13ax, fmaf(qa0, v13ay, fmaf(pb0, v13bx, fmaf(qb0, v13by, af.x + kk0))));
        float A1 = fmaf(pa1, v13ax, fmaf(qa1, v13ay, fmaf(pb1, v13bx, fmaf(qb1, v13by, af.y + kk1))));
        float A2 = fmaf(pa2, v13ax, fmaf(qa2, v13ay, fmaf(pb2, v13bx, fmaf(qb2, v13by, af.z + kk2))));
        float A3 = fmaf(pa3, v13ax, fmaf(qa3, v13ay, fmaf(pb3, v13bx, fmaf(qb3, v13by, af.w + kk3))));
        float vax = fmaf(R00, v13ax, fmaf(R01, v13ay, rc0));
        float vay = fmaf(R10, v13ax, fmaf(R11, v13ay, rc1));
        float vbx = fmaf(R00, v13bx, fmaf(R01, v13by, rc0));
        float vby = fmaf(R10, v13bx, fmaf(R11, v13by, rc1));

        const unsigned p_base = (Pb + it) | (w << 13) | (rr << 16);

        // suffix enumeration: b1 = s19 (level 18), b2 = s20 (level 19)
        #pragma unroll
        for (unsigned u = 0; u < 4; ++u) {
            const unsigned b1 = u & 1u, b2 = (u >> 1) & 1u;

            float vs18x = b1 ? vbx : vax;
            float vs18y = b1 ? vby : vay;
            float m00 = M18[b1 * 6 + 0], m01 = M18[b1 * 6 + 1];
            float m10 = M18[b1 * 6 + 2], m11 = M18[b1 * 6 + 3];
            float c0  = M18[b1 * 6 + 4], c1  = M18[b1 * 6 + 5];
            float pax = fmaf(m00, vax, fmaf(m01, vay, c0));
            float pay = fmaf(m10, vax, fmaf(m11, vay, c1));
            float pbx = fmaf(m00, vbx, fmaf(m01, vby, c0));
            float pby = fmaf(m10, vbx, fmaf(m11, vby, c1));

            float vs19x = b2 ? pbx : pax;
            float vs19y = b2 ? pby : pay;
            m00 = M19[b2 * 6 + 0]; m01 = M19[b2 * 6 + 1];
            m10 = M19[b2 * 6 + 2]; m11 = M19[b2 * 6 + 3];
            c0  = M19[b2 * 6 + 4]; c1  = M19[b2 * 6 + 5];
            float qax = fmaf(m00, pax, fmaf(m01, pay, c0));
            float qay = fmaf(m10, pax, fmaf(m11, pay, c1));
            float qbx = fmaf(m00, pbx, fmaf(m01, pby, c0));
            float qby = fmaf(m10, pbx, fmaf(m11, pby, c1));

            float P0 = fmaf(u19a.x, vs19x, fmaf(u19a.y, vs19y,
                       fmaf(u18a.x, vs18x, fmaf(u18a.y, vs18y, A0))));
            float P1 = fmaf(u19b.x, vs19x, fmaf(u19b.y, vs19y,
                       fmaf(u18b.x, vs18x, fmaf(u18b.y, vs18y, A1))));
            float P2 = fmaf(u19c.x, vs19x, fmaf(u19c.y, vs19y,
                       fmaf(u18c.x, vs18x, fmaf(u18c.y, vs18y, A2))));
            float P3 = fmaf(u19d.x, vs19x, fmaf(u19d.y, vs19y,
                       fmaf(u18d.x, vs18x, fmaf(u18d.y, vs18y, A3))));

            unsigned p = p_base | (b1 << 18) | (b2 << 19);
            float* o = out + (size_t)p * OUT_DIM + c4 * 4;

            float4 r0, r1;
            r0.x = fmaf(u20a.x, qax, fmaf(u20a.y, qay, P0));
            r0.y = fmaf(u20b.x, qax, fmaf(u20b.y, qay, P1));
            r0.z = fmaf(u20c.x, qax, fmaf(u20c.y, qay, P2));
            r0.w = fmaf(u20d.x, qax, fmaf(u20d.y, qay, P3));
            r1.x = fmaf(u20a.x, qbx, fmaf(u20a.y, qby, P0));
            r1.y = fmaf(u20b.x, qbx, fmaf(u20b.y, qby, P1));
            r1.z = fmaf(u20c.x, qbx, fmaf(u20c.y, qby, P2));
            r1.w = fmaf(u20d.x, qbx, fmaf(u20d.y, qby, P3));

            __stcs(reinterpret_cast<float4*>(o), r0);
            __stcs(reinterpret_cast<float4*>(o + ((size_t)1u << 20) * OUT_DIM), r1);
        }
    }
}

// ---------------------------------------------------------------------------
extern "C" void kernel_launch(void* const* d_in, const int* in_sizes, int n_in,
                              void* d_out, int out_size)
{
    const float* x    = (const float*)d_in[0];
    const float* wl   = (const float*)d_in[1];
    const float* wr   = (const float*)d_in[2];
    const float* bl   = (const float*)d_in[3];
    const float* br   = (const float*)d_in[4];
    const float* tl   = (const float*)d_in[5];
    const float* tr   = (const float*)d_in[6];
    const float* tbl  = (const float*)d_in[7];
    const float* tbr  = (const float*)d_in[8];
    const float* w0   = (const float*)d_in[9];
    const float* wout = (const float*)d_in[10];
    const float* ob   = (const float*)d_in[11];

    precompute_kernel<<<N_PRE * N_PART, 256>>>(x, wl, wr, bl, br, w0, ob);

    tree_kernel<<<(1 << BLK_BITS) / PPB, 256>>>(tl, tr, tbl, tbr, wout, (float*)d_out);
}

// round 17
// speedup vs baseline: 1.1583x; 1.0212x over previous
#include <cuda_runtime.h>

#define T_LEVELS    21
#define IN_DIM      4096
#define OUT_DIM     32
#define BLK_BITS    13         // levels 0..12, bits of prefix P
#define PPB         8          // prefixes per block (= warps per block)
#define N_PRE       (4 + OUT_DIM)
#define N_PART      4          // precompute partial splits per row

// Scratch: partial dot products (allowed: __device__ global, no alloc).
__device__ float g_part[N_PRE * N_PART];

// ---------------------------------------------------------------------------
// Kernel 1: 36 dot products of x (4096) with rows of in_left/in_right/out_layer0,
// split 4-ways per row for latency (144 fully-parallel small blocks).
// ---------------------------------------------------------------------------
__global__ void precompute_kernel(const float* __restrict__ x,
                                  const float* __restrict__ wl,
                                  const float* __restrict__ wr,
                                  const float* __restrict__ bl,
                                  const float* __restrict__ br,
                                  const float* __restrict__ w0,
                                  const float* __restrict__ ob)
{
    int r = blockIdx.x >> 2;       // 0..35
    int j = blockIdx.x & 3;        // part 0..3
    const float* src;
    if (r < 2)       src = wl + r * IN_DIM;
    else if (r < 4)  src = wr + (r - 2) * IN_DIM;
    else             src = w0 + (r - 4) * IN_DIM;

    const float4* x4 = reinterpret_cast<const float4*>(x) + j * 256;
    const float4* s4 = reinterpret_cast<const float4*>(src) + j * 256;
    float4 a = x4[threadIdx.x], b = s4[threadIdx.x];
    float s = fmaf(a.x, b.x, fmaf(a.y, b.y, fmaf(a.z, b.z, a.w * b.w)));

    __shared__ float red[8];
    #pragma unroll
    for (int o = 16; o > 0; o >>= 1) s += __shfl_down_sync(0xffffffffu, s, o);
    if ((threadIdx.x & 31) == 0) red[threadIdx.x >> 5] = s;
    __syncthreads();
    if (threadIdx.x == 0) {
        float tot = 0.0f;
        #pragma unroll
        for (int ww = 0; ww < 8; ww++) tot += red[ww];
        if (j == 0) {
            if (r < 2)      tot += bl[r];
            else if (r < 4) tot += br[r - 2];
            else            tot += ob[r - 4];
        }
        g_part[r * N_PART + j] = tot;
    }
}

// ---------------------------------------------------------------------------
// Kernel 2 (best-family body; stores switched __stcs -> __stwt):
// hierarchical binary-tree expansion, 8 prefixes per block.
//   Phase 1 (parallel): warp w computes the 13-level checkpoint for prefix
//       P = blockIdx*8 + w into s_A13[w]/s_v13[w].
//   Per-thread precompute: levels 13..17 (branch bits w, rr it-invariant)
//       composed into one affine map:
//          v18    = R·v13 + r
//          A18[c] = A13[c] + pa_c·vax + qa_c·vay + pb_c·vbx + qb_c·vby + k_c
//   Phase 2 (it=0..7): 2×LDS.128 + ~28 FMA to level 18, then the fully
//       register-hoisted suffix (levels 18..20) emits 8 rows via STG.128.
// Row index: p = (Pb+it) | (w<<13) | (rr<<16) | (b1<<18) | (b2<<19), leaf=bit20.
// Store: 8 lanes (c4 = lane&7) cover one full 128B row line; __stwt streams
// the write-once output past L2 (never read back -> no reason to allocate).
// ---------------------------------------------------------------------------
__global__ void __launch_bounds__(256, 2)
tree_kernel(const float* __restrict__ tl,   // (21,2,2)
            const float* __restrict__ tr,   // (21,2,2)
            const float* __restrict__ tbl,  // (21,2)
            const float* __restrict__ tbr,  // (21,2)
            const float* __restrict__ wout, // (21,32,2)
            float* __restrict__ out)
{
    __shared__ float s_wout[T_LEVELS * 64];  // [k][c][j]
    __shared__ float s_tree[T_LEVELS * 12];  // [k][branch]{m00,m01,m10,m11,b0,b1}
    __shared__ float s_pre[N_PRE];
    __shared__ __align__(16) float s_A13[PPB][OUT_DIM];
    __shared__ __align__(16) float s_v13[PPB][4];

    for (int i = threadIdx.x; i < T_LEVELS * 64; i += blockDim.x)
        s_wout[i] = wout[i];
    for (int i = threadIdx.x; i < T_LEVELS * 12; i += blockDim.x) {
        int k = i / 12, rem = i % 12, b = rem / 6, e = rem % 6;
        const float* M = b ? tr  : tl;
        const float* B = b ? tbr : tbl;
        s_tree[i] = (e < 4) ? M[k * 4 + e] : B[k * 2 + (e - 4)];
    }
    for (int i = threadIdx.x; i < N_PRE; i += blockDim.x)
        s_pre[i] = g_part[i * N_PART + 0] + g_part[i * N_PART + 1]
                 + g_part[i * N_PART + 2] + g_part[i * N_PART + 3];
    __syncthreads();

    const float2* s_wout2 = reinterpret_cast<const float2*>(s_wout);
    const unsigned w    = threadIdx.x >> 5;        // warp id: phase-1 owner AND level 13..15 bits
    const unsigned lane = threadIdx.x & 31u;
    const unsigned Pb   = blockIdx.x * PPB;

    // ---- phase 1 (parallel): warp w computes checkpoint for prefix Pb + w ----
    {
        const unsigned P = Pb + w;
        int c = lane;                               // lane = channel
        float A = s_pre[4 + c];
        float vax = s_pre[0], vay = s_pre[2];
        float vbx = s_pre[1], vby = s_pre[3];
        #pragma unroll 1
        for (int k = 0; k < BLK_BITS; k++) {
            unsigned b = (P >> k) & 1u;
            float2 wv = s_wout2[k * 32 + c];
            float vsx = b ? vbx : vax;
            float vsy = b ? vby : vay;
            A = fmaf(wv.x, vsx, fmaf(wv.y, vsy, A));
            const float* M = s_tree + k * 12 + b * 6;
            float m00 = M[0], m01 = M[1], m10 = M[2], m11 = M[3], c0 = M[4], c1 = M[5];
            float nax = fmaf(m00, vax, fmaf(m01, vay, c0));
            float nay = fmaf(m10, vax, fmaf(m11, vay, c1));
            float nbx = fmaf(m00, vbx, fmaf(m01, vby, c0));
            float nby = fmaf(m10, vbx, fmaf(m11, vby, c1));
            vax = nax; vay = nay; vbx = nbx; vby = nby;
        }
        s_A13[w][c] = A;
        if (lane == 0) {
            float4 v4; v4.x = vax; v4.y = vay; v4.z = vbx; v4.w = vby;
            *reinterpret_cast<float4*>(&s_v13[w][0]) = v4;
        }
    }

    const unsigned c4 = lane & 7u;                 // channel group (4 channels)
    const unsigned rr = lane >> 3;                 // 2 bits: levels 16..17

    // ---- per-thread affine composition of levels 13..17 (it-invariant) ----
    float R00 = 1.f, R01 = 0.f, R10 = 0.f, R11 = 1.f, rc0 = 0.f, rc1 = 0.f;
    float pa0 = 0.f, pa1 = 0.f, pa2 = 0.f, pa3 = 0.f;
    float qa0 = 0.f, qa1 = 0.f, qa2 = 0.f, qa3 = 0.f;
    float pb0 = 0.f, pb1 = 0.f, pb2 = 0.f, pb3 = 0.f;
    float qb0 = 0.f, qb1 = 0.f, qb2 = 0.f, qb3 = 0.f;
    float kk0 = 0.f, kk1 = 0.f, kk2 = 0.f, kk3 = 0.f;
    #pragma unroll
    for (int j = 0; j < 5; j++) {
        const int k = BLK_BITS + j;                 // 13..17
        unsigned b = (j < 3) ? ((w >> j) & 1u) : ((rr >> (j - 3)) & 1u);
        float sA = b ? 0.f : 1.f;
        float sB = b ? 1.f : 0.f;
        const float2* W = s_wout2 + k * 32 + c4 * 4;
        #pragma unroll
        for (int i = 0; i < 4; i++) {
            float2 w2 = W[i];
            float wRx = fmaf(w2.x, R00, w2.y * R10);
            float wRy = fmaf(w2.x, R01, w2.y * R11);
            float kc  = fmaf(w2.x, rc0, w2.y * rc1);
            float* PA = (i == 0) ? &pa0 : (i == 1) ? &pa1 : (i == 2) ? &pa2 : &pa3;
            float* QA = (i == 0) ? &qa0 : (i == 1) ? &qa1 : (i == 2) ? &qa2 : &qa3;
            float* PB = (i == 0) ? &pb0 : (i == 1) ? &pb1 : (i == 2) ? &pb2 : &pb3;
            float* QB = (i == 0) ? &qb0 : (i == 1) ? &qb1 : (i == 2) ? &qb2 : &qb3;
            float* KK = (i == 0) ? &kk0 : (i == 1) ? &kk1 : (i == 2) ? &kk2 : &kk3;
            *PA = fmaf(sA, wRx, *PA);
            *QA = fmaf(sA, wRy, *QA);
            *PB = fmaf(sB, wRx, *PB);
            *QB = fmaf(sB, wRy, *QB);
            *KK += kc;
        }
        const float* M = s_tree + k * 12 + b * 6;
        float m00 = M[0], m01 = M[1], m10 = M[2], m11 = M[3], c0 = M[4], c1 = M[5];
        float n00 = fmaf(m00, R00, m01 * R10), n01 = fmaf(m00, R01, m01 * R11);
        float n10 = fmaf(m10, R00, m11 * R10), n11 = fmaf(m10, R01, m11 * R11);
        float nr0 = fmaf(m00, rc0, fmaf(m01, rc1, c0));
        float nr1 = fmaf(m10, rc0, fmaf(m11, rc1, c1));
        R00 = n00; R01 = n01; R10 = n10; R11 = n11; rc0 = nr0; rc1 = nr1;
    }

    // ---- hoist ALL suffix constants (levels 18..20) into registers ----
    const float2* W18 = s_wout2 + 18 * 32 + c4 * 4;
    const float2* W19 = s_wout2 + 19 * 32 + c4 * 4;
    const float2* W20 = s_wout2 + 20 * 32 + c4 * 4;
    float2 u18a = W18[0], u18b = W18[1], u18c = W18[2], u18d = W18[3];
    float2 u19a = W19[0], u19b = W19[1], u19c = W19[2], u19d = W19[3];
    float2 u20a = W20[0], u20b = W20[1], u20c = W20[2], u20d = W20[3];
    float M18[12], M19[12];
    #pragma unroll
    for (int i = 0; i < 12; i++) M18[i] = s_tree[18 * 12 + i];
    #pragma unroll
    for (int i = 0; i < 12; i++) M19[i] = s_tree[19 * 12 + i];

    __syncthreads();

    // ---- phase 2: expand each of the 8 checkpoints ----
    #pragma unroll 1
    for (int it = 0; it < PPB; ++it) {
        const float4 af = *reinterpret_cast<const float4*>(&s_A13[it][c4 * 4]);
        const float4 vf = *reinterpret_cast<const float4*>(&s_v13[it][0]);
        const float v13ax = vf.x, v13ay = vf.y, v13bx = vf.z, v13by = vf.w;

        // jump to level 18 via the composed affine map
        float A0 = fmaf(pa0, v13ax, fmaf(qa0, v13ay, fmaf(pb0, v13bx, fmaf(qb0, v13by, af.x + kk0))));
        float A1 = fmaf(pa1, v13ax, fmaf(qa1, v13ay, fmaf(pb1, v13bx, fmaf(qb1, v13by, af.y + kk1))));
        float A2 = fmaf(pa2, v13ax, fmaf(qa2, v13ay, fmaf(pb2, v13bx, fmaf(qb2, v13by, af.z + kk2))));
        float A3 = fmaf(pa3, v13ax, fmaf(qa3, v13ay, fmaf(pb3, v13bx, fmaf(qb3, v13by, af.w + kk3))));
        float vax = fmaf(R00, v13ax, fmaf(R01, v13ay, rc0));
        float vay = fmaf(R10, v13ax, fmaf(R11, v13ay, rc1));
        float vbx = fmaf(R00, v13bx, fmaf(R01, v13by, rc0));
        float vby = fmaf(R10, v13bx, fmaf(R11, v13by, rc1));

        const unsigned p_base = (Pb + it) | (w << 13) | (rr << 16);

        // suffix enumeration: b1 = s19 (level 18), b2 = s20 (level 19)
        #pragma unroll
        for (unsigned u = 0; u < 4; ++u) {
            const unsigned b1 = u & 1u, b2 = (u >> 1) & 1u;

            float vs18x = b1 ? vbx : vax;
            float vs18y = b1 ? vby : vay;
            float m00 = M18[b1 * 6 + 0], m01 = M18[b1 * 6 + 1];
            float m10 = M18[b1 * 6 + 2], m11 = M18[b1 * 6 + 3];
            float c0  = M18[b1 * 6 + 4], c1  = M18[b1 * 6 + 5];
            float pax = fmaf(m00, vax, fmaf(m01, vay, c0));
            float pay = fmaf(m10, vax, fmaf(m11, vay, c1));
            float pbx = fmaf(m00, vbx, fmaf(m01, vby, c0));
            float pby = fmaf(m10, vbx, fmaf(m11, vby, c1));

            float vs19x = b2 ? pbx : pax;
            float vs19y = b2 ? pby : pay;
            m00 = M19[b2 * 6 + 0]; m01 = M19[b2 * 6 + 1];
            m10 = M19[b2 * 6 + 2]; m11 = M19[b2 * 6 + 3];
            c0  = M19[b2 * 6 + 4]; c1  = M19[b2 * 6 + 5];
            float qax = fmaf(m00, pax, fmaf(m01, pay, c0));
            float qay = fmaf(m10, pax, fmaf(m11, pay, c1));
            float qbx = fmaf(m00, pbx, fmaf(m01, pby, c0));
            float qby = fmaf(m10, pbx, fmaf(m11, pby, c1));

            float P0 = fmaf(u19a.x, vs19x, fmaf(u19a.y, vs19y,
                       fmaf(u18a.x, vs18x, fmaf(u18a.y, vs18y, A0))));
            float P1 = fmaf(u19b.x, vs19x, fmaf(u19b.y, vs19y,
                       fmaf(u18b.x, vs18x, fmaf(u18b.y, vs18y, A1))));
            float P2 = fmaf(u19c.x, vs19x, fmaf(u19c.y, vs19y,
                       fmaf(u18c.x, vs18x, fmaf(u18c.y, vs18y, A2))));
            float P3 = fmaf(u19d.x, vs19x, fmaf(u19d.y, vs19y,
                       fmaf(u18d.x, vs18x, fmaf(u18d.y, vs18y, A3))));

            unsigned p = p_base | (b1 << 18) | (b2 << 19);
            float* o = out + (size_t)p * OUT_DIM + c4 * 4;

            float4 r0, r1;
            r0.x = fmaf(u20a.x, qax, fmaf(u20a.y, qay, P0));
            r0.y = fmaf(u20b.x, qax, fmaf(u20b.y, qay, P1));
            r0.z = fmaf(u20c.x, qax, fmaf(u20c.y, qay, P2));
            r0.w = fmaf(u20d.x, qax, fmaf(u20d.y, qay, P3));
            r1.x = fmaf(u20a.x, qbx, fmaf(u20a.y, qby, P0));
            r1.y = fmaf(u20b.x, qbx, fmaf(u20b.y, qby, P1));
            r1.z = fmaf(u20c.x, qbx, fmaf(u20c.y, qby, P2));
            r1.w = fmaf(u20d.x, qbx, fmaf(u20d.y, qby, P3));

            __stwt(reinterpret_cast<float4*>(o), r0);
            __stwt(reinterpret_cast<float4*>(o + ((size_t)1u << 20) * OUT_DIM), r1);
        }
    }
}

// ---------------------------------------------------------------------------
extern "C" void kernel_launch(void* const* d_in, const int* in_sizes, int n_in,
                              void* d_out, int out_size)
{
    const float* x    = (const float*)d_in[0];
    const float* wl   = (const float*)d_in[1];
    const float* wr   = (const float*)d_in[2];
    const float* bl   = (const float*)d_in[3];
    const float* br   = (const float*)d_in[4];
    const float* tl   = (const float*)d_in[5];
    const float* tr   = (const float*)d_in[6];
    const float* tbl  = (const float*)d_in[7];
    const float* tbr  = (const float*)d_in[8];
    const float* w0   = (const float*)d_in[9];
    const float* wout = (const float*)d_in[10];
    const float* ob   = (const float*)d_in[11];

    precompute_kernel<<<N_PRE * N_PART, 256>>>(x, wl, wr, bl, br, w0, ob);

    tree_kernel<<<(1 << BLK_BITS) / PPB, 256>>>(tl, tr, tbl, tbr, wout, (float*)d_out);
}